// round 1
// baseline (speedup 1.0000x reference)
#include <cuda_runtime.h>
#include <math.h>

#define COL 14
#define NJ 14
#define NPIX 196
#define NB 8192
#define NJOINT (NB * NJ)          // 114688
#define THREADS 256
#define NWARPS 8
#define JPW 8                      // joints per warp
#define NBLOCKS (NJOINT / (NWARPS * JPW))   // 1792 exactly

__device__ double g_acc[3];        // d1sum, d2sum, cnt
__device__ float  g_GT[NPIX];      // G transposed: g_GT[c*14+r] = G[r][c]
__device__ float  g_cmin[COL];
__device__ float  g_cmax[COL];

// Build Gaussian matrix exactly like the numpy reference (fp64, then cast),
// and zero the global accumulators. One block, 256 threads.
__global__ void init_kernel() {
    int tid = threadIdx.x;
    if (tid < 3) g_acc[tid] = 0.0;

    // w[k] = exp(-0.5*(k-4)^2), normalized, in double (matches numpy)
    double w[9];
    double ws = 0.0;
    #pragma unroll
    for (int k = 0; k < 9; ++k) { w[k] = exp(-0.5 * (double)((k - 4) * (k - 4))); ws += w[k]; }
    #pragma unroll
    for (int k = 0; k < 9; ++k) w[k] /= ws;

    if (tid < NPIX) {
        int r = tid / COL, c = tid % COL;   // G[r][c]
        double s = 0.0;
        #pragma unroll
        for (int k = 0; k < 9; ++k) {
            int rr = r + k;  // row in padded identity, pad=4, 'symmetric'
            int m = (rr < 4) ? (3 - rr) : ((rr > 17) ? (31 - rr) : (rr - 4));
            if (m == c) s += w[k];
        }
        g_GT[c * COL + r] = (float)s;
    }
    __syncthreads();
    if (tid < COL) {
        float mn = 1e30f, mx = -1e30f;
        for (int r = 0; r < COL; ++r) {
            float gv = g_GT[tid * COL + r];
            mn = fminf(mn, gv);
            mx = fmaxf(mx, gv);
        }
        g_cmin[tid] = mn;
        g_cmax[tid] = mx;
    }
}

__global__ __launch_bounds__(THREADS) void main_kernel(
    const float* __restrict__ outp,
    const float* __restrict__ t,
    const float* __restrict__ v)
{
    __shared__ float sGT[NPIX];
    __shared__ float scmin[COL], scmax[COL];
    __shared__ double sred[NWARPS][3];

    int tid = threadIdx.x;
    if (tid < NPIX) sGT[tid] = g_GT[tid];
    if (tid < COL) { scmin[tid] = g_cmin[tid]; scmax[tid] = g_cmax[tid]; }
    __syncthreads();

    const int lane = tid & 31;
    const int warp = tid >> 5;
    const int gw = blockIdx.x * NWARPS + warp;

    double d1 = 0.0, d2 = 0.0, cnt = 0.0;

    for (int k = 0; k < JPW; ++k) {
        const int joint = gw * JPW + k;          // < NJOINT by construction
        const int b = joint / NJ;
        const int j = joint - b * NJ;
        const float* hb = outp + ((size_t)b * (3 * NJ) + j) * NPIX;

        const float t0 = t[joint * 2 + 0];
        const float t1 = t[joint * 2 + 1];
        const float v0 = v[joint * 2 + 0];

        const int xi = (int)(t0 * 14.0f);
        const int yi = (int)(t1 * 14.0f);
        const bool inb = (xi >= 0) && (xi <= COL - 1) && (yi >= 0) && (yi <= COL - 1);
        const bool vis = ((int)v0) == 1;
        const bool scat = vis && inb;
        const float vef = (vis && !inb) ? 0.0f : v0;       // v_eff (channels equal)
        const float veI = (((int)vef) == 1) ? 1.0f : 0.0f; // vis_eff as 0/1 float

        const int yic = min(max(yi, 0), COL - 1);
        const int xic = min(max(xi, 0), COL - 1);
        const float mn = scmin[yic] * scmin[xic];
        const float mx = scmax[yic] * scmax[xic];
        const float inv = scat ? (1.0f / (mx - mn)) : 0.0f;
        const float nmi = -mn * inv;             // !scat => tt_norm == 0 automatically

        // ---- pass 1: coalesced load + local argmax ----
        float hv[7];
        float best = -INFINITY;
        int bidx = 0;
        #pragma unroll
        for (int i = 0; i < 7; ++i) {
            int e = lane + 32 * i;
            float hval = (i < 6 || lane < 4) ? hb[e] : -INFINITY;
            hv[i] = hval;
            if (hval > best) { best = hval; bidx = e; }   // ascending e => first max kept
        }
        // warp argmax, tie -> lower index (matches jnp.argmax first occurrence)
        #pragma unroll
        for (int off = 16; off; off >>= 1) {
            float ov = __shfl_xor_sync(0xffffffffu, best, off);
            int   oi = __shfl_xor_sync(0xffffffffu, bidx, off);
            if (ov > best || (ov == best && oi < bidx)) { best = ov; bidx = oi; }
        }

        // ---- scattered gathers (issue early, used after pass 2) ----
        float ox = 0.0f, oy = 0.0f;
        if (lane == 0) {
            const size_t ob = (size_t)b * (3 * NJ) * NPIX;
            ox = outp[ob + (size_t)(NJ + j) * NPIX + bidx];
            oy = outp[ob + (size_t)(2 * NJ + j) * NPIX + bidx];
        }
        const int yc = bidx / COL;
        const int xc = bidx - yc * COL;

        // ---- pass 2: sum (h - tt_norm)^2 with row-0 visibility mask ----
        const float* gyrow = sGT + yic * COL;
        const float* gxrow = sGT + xic * COL;
        float s = 0.0f;
        #pragma unroll
        for (int i = 0; i < 7; ++i) {
            int e = lane + 32 * i;
            if (i < 6 || lane < 4) {
                int y = e / COL;
                int x = e - y * COL;
                float tt = gyrow[y] * gxrow[x];
                float ttn = fmaf(tt, inv, nmi);          // (tt-mn)/(mx-mn) or 0
                float d = hv[i] - ttn;
                if (i == 0 && lane < COL) d *= veI;      // y==0 row mask
                s = fmaf(d, d, s);
            }
        }
        #pragma unroll
        for (int off = 16; off; off >>= 1)
            s += __shfl_xor_sync(0xffffffffu, s, off);

        if (lane == 0) {
            d1 += (double)s;
            float px = (ox + (float)xc) * (1.0f / 14.0f);
            float py = (oy + (float)yc) * (1.0f / 14.0f);
            float dx = (px - t0) * vef;
            float dy = (py - t1) * vef;
            d2 += (double)(dx * dx + dy * dy);
            cnt += (double)veI;
        }
    }

    if (lane == 0) { sred[warp][0] = d1; sred[warp][1] = d2; sred[warp][2] = cnt; }
    __syncthreads();
    if (tid == 0) {
        double a = 0.0, bb = 0.0, c = 0.0;
        for (int w = 0; w < NWARPS; ++w) { a += sred[w][0]; bb += sred[w][1]; c += sred[w][2]; }
        atomicAdd(&g_acc[0], a);
        atomicAdd(&g_acc[1], bb);
        atomicAdd(&g_acc[2], c);
    }
}

__global__ void final_kernel(float* o) {
    // n2 == cnt exactly: v is a tiled 0/1 mask, sum over 2 channels / 2
    o[0] = (float)(g_acc[0] / g_acc[2] + g_acc[1] / g_acc[2]);
}

extern "C" void kernel_launch(void* const* d_in, const int* in_sizes, int n_in,
                              void* d_out, int out_size)
{
    const float* outp = (const float*)d_in[0];
    const float* t    = (const float*)d_in[1];
    const float* v    = (const float*)d_in[2];

    init_kernel<<<1, 256>>>();
    main_kernel<<<NBLOCKS, THREADS>>>(outp, t, v);
    final_kernel<<<1, 1>>>((float*)d_out);
}

// round 2
// speedup vs baseline: 1.2832x; 1.2832x over previous
#include <cuda_runtime.h>
#include <math.h>

#define COL 14
#define NJ 14
#define NPIX 196
#define NB 8192
#define NJOINT (NB * NJ)                 // 114688
#define THREADS 256
#define NWARPS 8
#define JPW 4                            // joints per warp
#define NBLOCKS (NJOINT / (NWARPS * JPW))  // 3584 exactly

struct GParams {
    float GT[NPIX];     // GT[c*14+r] = G[r][c]
    float cmin[COL];
    float cmax[COL];
};

__device__ double g_part[NBLOCKS * 3];   // per-block partials: d1, d2, cnt

__global__ __launch_bounds__(THREADS) void main_kernel(
    const float* __restrict__ outp,
    const float* __restrict__ t,
    const float* __restrict__ v,
    const GParams gp)
{
    __shared__ float sGT[NPIX];
    __shared__ float scmin[COL], scmax[COL];
    __shared__ double sred[NWARPS][3];

    int tid = threadIdx.x;
    if (tid < NPIX) sGT[tid] = gp.GT[tid];
    if (tid < COL) { scmin[tid] = gp.cmin[tid]; scmax[tid] = gp.cmax[tid]; }
    __syncthreads();

    const int lane = tid & 31;
    const int warp = tid >> 5;
    const int gw = blockIdx.x * NWARPS + warp;   // global warp id
    const int joint0 = gw * JPW;

    float d1 = 0.0f;            // per-lane fp32; each warp sums only 4*196 terms
    int bidx_arr[JPW];

    #pragma unroll
    for (int k = 0; k < JPW; ++k) {
        const int joint = joint0 + k;
        const int b = joint / NJ;
        const int j = joint - b * NJ;
        const float* hb = outp + ((size_t)b * (3 * NJ) + j) * NPIX;

        // ---- vectorized h load: 2x LDG.128 per joint ----
        float4 h0 = *reinterpret_cast<const float4*>(hb + 4 * lane);
        float4 h1 = make_float4(-INFINITY, -INFINITY, -INFINITY, -INFINITY);
        if (lane < 17) h1 = *reinterpret_cast<const float4*>(hb + 128 + 4 * lane);

        // ---- per-joint target params (uniform across warp) ----
        const float t0 = t[joint * 2 + 0];
        const float t1 = t[joint * 2 + 1];
        const float v0 = v[joint * 2 + 0];

        const int xi = (int)(t0 * 14.0f);
        const int yi = (int)(t1 * 14.0f);
        const bool inb = (xi >= 0) && (xi <= COL - 1) && (yi >= 0) && (yi <= COL - 1);
        const bool vis = ((int)v0) == 1;
        const bool scat = vis && inb;
        const float vef = (vis && !inb) ? 0.0f : v0;
        const float veI = (((int)vef) == 1) ? 1.0f : 0.0f;

        const int yic = min(max(yi, 0), COL - 1);
        const int xic = min(max(xi, 0), COL - 1);
        const float mn = scmin[yic] * scmin[xic];
        const float mx = scmax[yic] * scmax[xic];
        const float inv = scat ? (1.0f / (mx - mn)) : 0.0f;
        const float nmi = -mn * inv;              // !scat => tt_norm == 0

        const float* gyrow = sGT + yic * COL;
        const float* gxrow = sGT + xic * COL;

        // ---- fused argmax + d1 over both vectors ----
        float best = -INFINITY;
        int bidx = 0;
        float s = 0.0f;
        const float hv[8] = {h0.x, h0.y, h0.z, h0.w, h1.x, h1.y, h1.z, h1.w};
        #pragma unroll
        for (int c = 0; c < 8; ++c) {
            int e = (c < 4) ? (4 * lane + c) : (128 + 4 * lane + (c - 4));
            bool valid = (c < 4) || (lane < 17);
            float hval = hv[c];
            if (valid) {
                if (hval > best) { best = hval; bidx = e; }
                int y = e / COL;
                int x = e - y * COL;
                float tt = gyrow[y] * gxrow[x];
                float ttn = fmaf(tt, inv, nmi);
                float d = hval - ttn;
                if (y == 0) d *= veI;             // row-0 visibility mask
                s = fmaf(d, d, s);
            }
        }
        d1 += s;

        // warp argmax, tie -> lower index (jnp first-occurrence)
        #pragma unroll
        for (int off = 16; off; off >>= 1) {
            float ov = __shfl_xor_sync(0xffffffffu, best, off);
            int   oi = __shfl_xor_sync(0xffffffffu, bidx, off);
            if (ov > best || (ov == best && oi < bidx)) { best = ov; bidx = oi; }
        }
        bidx_arr[k] = bidx;   // uniform across warp
    }

    // warp-reduce d1
    #pragma unroll
    for (int off = 16; off; off >>= 1)
        d1 += __shfl_xor_sync(0xffffffffu, d1, off);

    // ---- phase B: deferred gathers, lanes 0..3 handle one joint each ----
    float d2 = 0.0f, cntf = 0.0f;
    if (lane < JPW) {
        const int joint = joint0 + lane;
        const int b = joint / NJ;
        const int j = joint - b * NJ;
        const int bidx = bidx_arr[0] * 0 +                 // force array in regs
            ((lane == 0) ? bidx_arr[0] : (lane == 1) ? bidx_arr[1] :
             (lane == 2) ? bidx_arr[2] : bidx_arr[3]);

        const size_t ob = (size_t)b * (3 * NJ) * NPIX;
        const float ox = outp[ob + (size_t)(NJ + j) * NPIX + bidx];
        const float oy = outp[ob + (size_t)(2 * NJ + j) * NPIX + bidx];

        const float t0 = t[joint * 2 + 0];
        const float t1 = t[joint * 2 + 1];
        const float v0 = v[joint * 2 + 0];
        const int xi = (int)(t0 * 14.0f);
        const int yi = (int)(t1 * 14.0f);
        const bool inb = (xi >= 0) && (xi <= COL - 1) && (yi >= 0) && (yi <= COL - 1);
        const bool vis = ((int)v0) == 1;
        const float vef = (vis && !inb) ? 0.0f : v0;
        const float veI = (((int)vef) == 1) ? 1.0f : 0.0f;

        const int yc = bidx / COL;
        const int xc = bidx - yc * COL;
        const float px = (ox + (float)xc) * (1.0f / 14.0f);
        const float py = (oy + (float)yc) * (1.0f / 14.0f);
        const float dx = (px - t0) * vef;
        const float dy = (py - t1) * vef;
        d2 = fmaf(dx, dx, dy * dy);
        cntf = veI;
    }
    #pragma unroll
    for (int off = 16; off; off >>= 1) {
        d2   += __shfl_xor_sync(0xffffffffu, d2, off);
        cntf += __shfl_xor_sync(0xffffffffu, cntf, off);
    }

    if (lane == 0) {
        sred[warp][0] = (double)d1;
        sred[warp][1] = (double)d2;
        sred[warp][2] = (double)cntf;
    }
    __syncthreads();
    if (tid == 0) {
        double a = 0.0, bb = 0.0, c = 0.0;
        #pragma unroll
        for (int w = 0; w < NWARPS; ++w) { a += sred[w][0]; bb += sred[w][1]; c += sred[w][2]; }
        g_part[blockIdx.x * 3 + 0] = a;
        g_part[blockIdx.x * 3 + 1] = bb;
        g_part[blockIdx.x * 3 + 2] = c;
    }
}

__global__ __launch_bounds__(256) void final_kernel(float* o) {
    __shared__ double sa[256], sb[256], sc[256];
    int tid = threadIdx.x;
    double a = 0.0, bb = 0.0, c = 0.0;
    for (int i = tid; i < NBLOCKS; i += 256) {
        a  += g_part[i * 3 + 0];
        bb += g_part[i * 3 + 1];
        c  += g_part[i * 3 + 2];
    }
    sa[tid] = a; sb[tid] = bb; sc[tid] = c;
    __syncthreads();
    for (int off = 128; off; off >>= 1) {
        if (tid < off) { sa[tid] += sa[tid + off]; sb[tid] += sb[tid + off]; sc[tid] += sc[tid + off]; }
        __syncthreads();
    }
    if (tid == 0)
        o[0] = (float)(sa[0] / sc[0] + sb[0] / sc[0]);   // n2 == cnt (tiled 0/1 mask)
}

extern "C" void kernel_launch(void* const* d_in, const int* in_sizes, int n_in,
                              void* d_out, int out_size)
{
    const float* outp = (const float*)d_in[0];
    const float* t    = (const float*)d_in[1];
    const float* v    = (const float*)d_in[2];

    // Host-side Gaussian matrix, fp64 exactly like the numpy reference.
    GParams gp;
    {
        double w[9], ws = 0.0;
        for (int k = 0; k < 9; ++k) { w[k] = exp(-0.5 * (double)((k - 4) * (k - 4))); ws += w[k]; }
        for (int k = 0; k < 9; ++k) w[k] /= ws;
        for (int r = 0; r < COL; ++r)
            for (int c = 0; c < COL; ++c) {
                double s = 0.0;
                for (int k = 0; k < 9; ++k) {
                    int rr = r + k;   // padded row, pad=4, 'symmetric'
                    int m = (rr < 4) ? (3 - rr) : ((rr > 17) ? (31 - rr) : (rr - 4));
                    if (m == c) s += w[k];
                }
                gp.GT[c * COL + r] = (float)s;
            }
        for (int c = 0; c < COL; ++c) {
            float mn = 1e30f, mx = -1e30f;
            for (int r = 0; r < COL; ++r) {
                float gv = gp.GT[c * COL + r];
                mn = fminf(mn, gv);
                mx = fmaxf(mx, gv);
            }
            gp.cmin[c] = mn;
            gp.cmax[c] = mx;
        }
    }

    main_kernel<<<NBLOCKS, THREADS>>>(outp, t, v, gp);
    final_kernel<<<1, 256>>>((float*)d_out);
}

// round 4
// speedup vs baseline: 1.9248x; 1.5000x over previous
#include <cuda_runtime.h>
#include <math.h>

#define COL 14
#define NJ 14
#define NPIX 196
#define NB 8192
#define NJOINT (NB * NJ)                   // 114688
#define THREADS 256
#define NWARPS 8
#define JPW 4
#define NBLOCKS (NJOINT / (NWARPS * JPW))  // 3584 exactly

struct GParams {
    float GT[NPIX];     // GT[c*14+r] = G[r][c]  (row c of G^T)
    float cmin[COL];
    float cmax[COL];
};

__device__ float    g_d1[NBLOCKS];
__device__ float    g_d2[NBLOCKS];
__device__ float    g_cnt[NBLOCKS];
__device__ unsigned g_ticket;   // zero-init at load; net-zero per run (last block resets)

// ---- packed f32x2 helpers (Blackwell) ----
__device__ __forceinline__ unsigned long long pack2(float lo, float hi) {
    unsigned long long r;
    asm("mov.b64 %0,{%1,%2};" : "=l"(r) : "f"(lo), "f"(hi));
    return r;
}
__device__ __forceinline__ void unpack2(unsigned long long p, float& lo, float& hi) {
    asm("mov.b64 {%0,%1},%2;" : "=f"(lo), "=f"(hi) : "l"(p));
}
__device__ __forceinline__ unsigned long long mul2(unsigned long long a, unsigned long long b) {
    unsigned long long r;
    asm("mul.rn.f32x2 %0,%1,%2;" : "=l"(r) : "l"(a), "l"(b));
    return r;
}
__device__ __forceinline__ unsigned long long add2(unsigned long long a, unsigned long long b) {
    unsigned long long r;
    asm("add.rn.f32x2 %0,%1,%2;" : "=l"(r) : "l"(a), "l"(b));
    return r;
}
__device__ __forceinline__ unsigned long long fma2(unsigned long long a, unsigned long long b,
                                                   unsigned long long c) {
    unsigned long long r;
    asm("fma.rn.f32x2 %0,%1,%2,%3;" : "=l"(r) : "l"(a), "l"(b), "l"(c));
    return r;
}

__global__ __launch_bounds__(THREADS) void main_kernel(
    const float* __restrict__ outp,
    const float* __restrict__ t,
    const float* __restrict__ v,
    float* __restrict__ o,
    const GParams gp)
{
    __shared__ float sGT[NPIX];
    __shared__ float scmin[COL], scmax[COL];
    __shared__ float sred[NWARPS][3];
    __shared__ int   s_last;
    __shared__ double dra[NWARPS], drb[NWARPS], drc[NWARPS];

    const int tid = threadIdx.x;
    if (tid < NPIX) sGT[tid] = gp.GT[tid];
    if (tid < COL) { scmin[tid] = gp.cmin[tid]; scmax[tid] = gp.cmax[tid]; }
    __syncthreads();

    const int lane = tid & 31;
    const int warp = tid >> 5;
    const int gw = blockIdx.x * NWARPS + warp;
    const int joint0 = gw * JPW;
    const bool hasB = lane < 17;

    // ---- per-lane element geometry (joint-independent) ----
    int yE[8], xE[8], eE[8];
    bool r0[4];
    #pragma unroll
    for (int c = 0; c < 4; ++c) {
        int e = 4 * lane + c;
        eE[c] = e; yE[c] = e / COL; xE[c] = e - yE[c] * COL;
        r0[c] = (e < COL);
    }
    #pragma unroll
    for (int c = 0; c < 4; ++c) {
        int e = 128 + 4 * lane + c;
        int ec = hasB ? e : 0;                // clamp so smem idx stays valid
        eE[4 + c] = e; yE[4 + c] = ec / COL; xE[4 + c] = ec - (ec / COL) * COL;
    }

    // ---- t/v for 4 joints: 4x LDG.128 (uniform broadcast) ----
    const float4 tA = *reinterpret_cast<const float4*>(t + 8 * (size_t)gw);
    const float4 tB = *reinterpret_cast<const float4*>(t + 8 * (size_t)gw + 4);
    const float4 vA = *reinterpret_cast<const float4*>(v + 8 * (size_t)gw);
    const float4 vB = *reinterpret_cast<const float4*>(v + 8 * (size_t)gw + 4);
    const float t0k[4] = {tA.x, tA.z, tB.x, tB.z};
    const float t1k[4] = {tA.y, tA.w, tB.y, tB.w};
    const float v0k[4] = {vA.x, vA.z, vB.x, vB.z};

    float d1 = 0.0f;
    int bidx_k[JPW];
    float vef_k[JPW], veI_k[JPW];

    int bb = joint0 / NJ;
    int jj = joint0 - bb * NJ;

    #pragma unroll
    for (int k = 0; k < JPW; ++k) {
        const float* hb = outp + ((size_t)bb * (3 * NJ) + jj) * NPIX;

        const float4 h0 = __ldcs(reinterpret_cast<const float4*>(hb + 4 * lane));
        float4 h1 = make_float4(-INFINITY, -INFINITY, -INFINITY, -INFINITY);
        if (hasB) h1 = __ldcs(reinterpret_cast<const float4*>(hb + 128 + 4 * lane));

        const float t0 = t0k[k], t1 = t1k[k], v0 = v0k[k];
        const int xi = (int)(t0 * 14.0f);
        const int yi = (int)(t1 * 14.0f);
        const bool inb = (xi >= 0) && (xi <= COL - 1) && (yi >= 0) && (yi <= COL - 1);
        const bool vis = ((int)v0) == 1;
        const bool scat = vis && inb;
        const float vef = (vis && !inb) ? 0.0f : v0;
        const float veI = (((int)vef) == 1) ? 1.0f : 0.0f;
        vef_k[k] = vef; veI_k[k] = veI;

        const int yic = min(max(yi, 0), COL - 1);
        const int xic = min(max(xi, 0), COL - 1);
        const float mn = scmin[yic] * scmin[xic];
        const float mx = scmax[yic] * scmax[xic];
        const float inv = scat ? (1.0f / (mx - mn)) : 0.0f;
        const float nmi = -mn * inv;          // !scat => ttn == 0 exactly

        const float* gyrow = sGT + yic * COL;
        const float* gxrow = sGT + xic * COL;

        const unsigned long long ninv2 = pack2(-inv, -inv);
        const unsigned long long nnmi2 = pack2(-nmi, -nmi);
        const float m0 = r0[0] ? veI : 1.0f;
        const float m1 = r0[1] ? veI : 1.0f;
        const float m2v = r0[2] ? veI : 1.0f;
        const float m3 = r0[3] ? veI : 1.0f;
        const unsigned long long mP0 = pack2(m0, m1);
        const unsigned long long mP1 = pack2(m2v, m3);

        const float hv[8] = {h0.x, h0.y, h0.z, h0.w, h1.x, h1.y, h1.z, h1.w};
        const unsigned long long h2[4] = {pack2(h0.x, h0.y), pack2(h0.z, h0.w),
                                          pack2(h1.x, h1.y), pack2(h1.z, h1.w)};

        // ---- d1 element math (packed f32x2) ----
        unsigned long long s2 = pack2(0.0f, 0.0f);
        #pragma unroll
        for (int p = 0; p < 2; ++p) {
            unsigned long long gy2 = pack2(gyrow[yE[2 * p]], gyrow[yE[2 * p + 1]]);
            unsigned long long gx2 = pack2(gxrow[xE[2 * p]], gxrow[xE[2 * p + 1]]);
            unsigned long long tt2 = mul2(gy2, gx2);
            unsigned long long hn2 = add2(h2[p], nnmi2);           // h - nmi
            unsigned long long dv2 = fma2(tt2, ninv2, hn2);        // h - (tt*inv + nmi)
            unsigned long long dm2 = mul2(dv2, (p == 0) ? mP0 : mP1);
            s2 = fma2(dm2, dm2, s2);
        }
        if (hasB) {
            #pragma unroll
            for (int p = 2; p < 4; ++p) {
                unsigned long long gy2 = pack2(gyrow[yE[2 * p]], gyrow[yE[2 * p + 1]]);
                unsigned long long gx2 = pack2(gxrow[xE[2 * p]], gxrow[xE[2 * p + 1]]);
                unsigned long long tt2 = mul2(gy2, gx2);
                unsigned long long hn2 = add2(h2[p], nnmi2);
                unsigned long long dv2 = fma2(tt2, ninv2, hn2);
                s2 = fma2(dv2, dv2, s2);
            }
        }
        float slo, shi; unpack2(s2, slo, shi);
        d1 += slo + shi;

        // ---- per-lane argmax: tree max + first-index select ----
        float b01 = fmaxf(hv[0], hv[1]), b23 = fmaxf(hv[2], hv[3]);
        float b45 = fmaxf(hv[4], hv[5]), b67 = fmaxf(hv[6], hv[7]);
        float best = fmaxf(fmaxf(b01, b23), fmaxf(b45, b67));
        int idx = 0x7fffffff;
        #pragma unroll
        for (int c = 7; c >= 0; --c)
            idx = (hv[c] == best) ? eE[c] : idx;   // -INF never equals finite best

        // ---- warp argmax via REDUX ----
        unsigned u = __float_as_uint(best);
        unsigned mono = ((int)u < 0) ? ~u : (u | 0x80000000u);
        unsigned mmax = __reduce_max_sync(0xffffffffu, mono);
        int cand = (mono == mmax) ? idx : 0x7fffffff;
        bidx_k[k] = __reduce_min_sync(0xffffffffu, cand);

        // advance (b, j)
        ++jj; if (jj == NJ) { jj = 0; ++bb; }
    }

    // warp-reduce d1
    #pragma unroll
    for (int off = 16; off; off >>= 1)
        d1 += __shfl_xor_sync(0xffffffffu, d1, off);

    // ---- phase B: deferred ox/oy gathers, lanes 0..3 (one joint each) ----
    float d2 = 0.0f, cntf = 0.0f;
    if (lane < JPW) {
        const int joint = joint0 + lane;
        const int b2 = joint / NJ;
        const int j2 = joint - b2 * NJ;
        const int bidx = (lane == 0) ? bidx_k[0] : (lane == 1) ? bidx_k[1]
                        : (lane == 2) ? bidx_k[2] : bidx_k[3];
        const float vef = (lane == 0) ? vef_k[0] : (lane == 1) ? vef_k[1]
                        : (lane == 2) ? vef_k[2] : vef_k[3];
        const float veI = (lane == 0) ? veI_k[0] : (lane == 1) ? veI_k[1]
                        : (lane == 2) ? veI_k[2] : veI_k[3];
        const float t0 = t0k[lane], t1 = t1k[lane];

        const size_t ob = (size_t)b2 * (3 * NJ) * NPIX;
        const float ox = outp[ob + (size_t)(NJ + j2) * NPIX + bidx];
        const float oy = outp[ob + (size_t)(2 * NJ + j2) * NPIX + bidx];

        const int yc = bidx / COL;
        const int xc = bidx - yc * COL;
        const float px = (ox + (float)xc) * (1.0f / 14.0f);
        const float py = (oy + (float)yc) * (1.0f / 14.0f);
        const float dx = (px - t0) * vef;
        const float dy = (py - t1) * vef;
        d2 = fmaf(dx, dx, dy * dy);
        cntf = veI;
    }
    // 4-lane reduce (lanes >=4 contribute zeros within their xor-groups)
    #pragma unroll
    for (int off = 1; off <= 2; off <<= 1) {
        d2   += __shfl_xor_sync(0xffffffffu, d2, off);
        cntf += __shfl_xor_sync(0xffffffffu, cntf, off);
    }

    if (lane == 0) { sred[warp][0] = d1; sred[warp][1] = d2; sred[warp][2] = cntf; }
    __syncthreads();

    if (tid == 0) {
        float a = 0.0f, bsum = 0.0f, c = 0.0f;
        #pragma unroll
        for (int w = 0; w < NWARPS; ++w) { a += sred[w][0]; bsum += sred[w][1]; c += sred[w][2]; }
        g_d1[blockIdx.x] = a;
        g_d2[blockIdx.x] = bsum;
        g_cnt[blockIdx.x] = c;
        __threadfence();
        unsigned old = atomicAdd(&g_ticket, 1u);
        s_last = (old == NBLOCKS - 1);
    }
    __syncthreads();

    // ---- last block: grid reduction (no separate kernel) ----
    if (s_last) {
        if (tid == 0) g_ticket = 0;          // net-zero per run
        __threadfence();
        double a = 0.0, bsum = 0.0, c = 0.0;
        for (int i = tid; i < NBLOCKS; i += THREADS) {
            a    += (double)g_d1[i];
            bsum += (double)g_d2[i];
            c    += (double)g_cnt[i];
        }
        #pragma unroll
        for (int off = 16; off; off >>= 1) {
            a    += __shfl_xor_sync(0xffffffffu, a, off);
            bsum += __shfl_xor_sync(0xffffffffu, bsum, off);
            c    += __shfl_xor_sync(0xffffffffu, c, off);
        }
        if (lane == 0) { dra[warp] = a; drb[warp] = bsum; drc[warp] = c; }
        __syncthreads();
        if (tid == 0) {
            double A = 0.0, B = 0.0, C = 0.0;
            #pragma unroll
            for (int w = 0; w < NWARPS; ++w) { A += dra[w]; B += drb[w]; C += drc[w]; }
            o[0] = (float)(A / C + B / C);   // n2 == cnt (v is a tiled 0/1 mask)
        }
    }
}

extern "C" void kernel_launch(void* const* d_in, const int* in_sizes, int n_in,
                              void* d_out, int out_size)
{
    const float* outp = (const float*)d_in[0];
    const float* t    = (const float*)d_in[1];
    const float* v    = (const float*)d_in[2];

    // Host-side Gaussian matrix, fp64 exactly like the numpy reference.
    GParams gp;
    {
        double w[9], ws = 0.0;
        for (int k = 0; k < 9; ++k) { w[k] = exp(-0.5 * (double)((k - 4) * (k - 4))); ws += w[k]; }
        for (int k = 0; k < 9; ++k) w[k] /= ws;
        for (int r = 0; r < COL; ++r)
            for (int c = 0; c < COL; ++c) {
                double s = 0.0;
                for (int k = 0; k < 9; ++k) {
                    int rr = r + k;   // padded row, pad=4, 'symmetric'
                    int m = (rr < 4) ? (3 - rr) : ((rr > 17) ? (31 - rr) : (rr - 4));
                    if (m == c) s += w[k];
                }
                gp.GT[c * COL + r] = (float)s;
            }
        for (int c = 0; c < COL; ++c) {
            float mn = 1e30f, mx = -1e30f;
            for (int r = 0; r < COL; ++r) {
                float gv = gp.GT[c * COL + r];
                mn = fminf(mn, gv);
                mx = fmaxf(mx, gv);
            }
            gp.cmin[c] = mn;
            gp.cmax[c] = mx;
        }
    }

    main_kernel<<<NBLOCKS, THREADS>>>(outp, t, v, (float*)d_out, gp);
}